// round 2
// baseline (speedup 1.0000x reference)
#include <cuda_runtime.h>
#include <cuda_bf16.h>

#define BATCH    65536
#define N_WIRES  4
#define N_LAYERS 3
#define BN_EPS   1e-5f

// Scratch (no cudaMalloc allowed): precomputed gates, BN accumulators, pre-BN outputs.
__device__ float g_M[96];             // [L=3][W=4][row=2][col=2][ri=2]
__device__ float g_acc[8];            // 4 sums + 4 sums-of-squares
__device__ float g_pre[BATCH * 4];    // pre-BN linear outputs

// ---------------------------------------------------------------------------
// Kernel 0: compute fused RX@RZ gate matrices from params; zero accumulators.
// ---------------------------------------------------------------------------
__global__ void prep_kernel(const float* __restrict__ params) {
    int t = threadIdx.x;
    if (t < 8) g_acc[t] = 0.0f;
    if (t < 12) {   // t = l*4 + w
        float t0 = params[t * 3 + 0];
        float t1 = params[t * 3 + 1];
        float c0, s0, c1, s1;
        sincosf(0.5f * t0, &s0, &c0);
        sincosf(0.5f * t1, &s1, &c1);
        // M = RX(t1) @ RZ(t0):
        // M00 = ( c1*c0, -c1*s0)   M01 = ( s1*s0, -s1*c0)
        // M10 = (-s1*s0, -s1*c0)   M11 = ( c1*c0,  c1*s0)
        float2* Mo = (float2*)g_M;
        Mo[t * 4 + 0] = make_float2( c1 * c0, -c1 * s0);
        Mo[t * 4 + 1] = make_float2( s1 * s0, -s1 * c0);
        Mo[t * 4 + 2] = make_float2(-s1 * s0, -s1 * c0);
        Mo[t * 4 + 3] = make_float2( c1 * c0,  c1 * s0);
    }
}

// ---------------------------------------------------------------------------
// Kernel 1: encode (chunk means) + 4-qubit statevector sim (16 lanes = 16
// amplitudes, 2 samples per warp) + Linear(4,4) + BN partial sums.
// ---------------------------------------------------------------------------
__global__ void __launch_bounds__(256) sim_kernel(const float* __restrict__ x,
                                                  const float* __restrict__ Wg,
                                                  const float* __restrict__ bg) {
    __shared__ float sM[96];
    __shared__ float sAcc[8];
    int tid = threadIdx.x;
    if (tid < 96) sM[tid] = g_M[tid];
    if (tid < 8)  sAcc[tid] = 0.0f;
    __syncthreads();

    int lane = tid & 31;
    int warp = tid >> 5;
    int sA = (blockIdx.x * 8 + warp) * 2;   // warp handles samples sA, sA+1

    // ---- encoding: mean of 4 chunks of 196 floats (49 float4 each) ----
    // lanes split into 4 groups of 8; group g sums chunk g (for both samples).
    const float4* x4 = (const float4*)x;
    int g  = lane >> 3;
    int j8 = lane & 7;
    const float4* pA = x4 + (size_t)sA * 196 + g * 49 + j8;
    float sum_a = 0.0f, sum_b = 0.0f;
#pragma unroll
    for (int it = 0; it < 6; it++) {
        float4 v = pA[it * 8];
        sum_a += (v.x + v.y) + (v.z + v.w);
        float4 u = pA[196 + it * 8];
        sum_b += (u.x + u.y) + (u.z + u.w);
    }
    if (j8 == 0) {
        float4 v = pA[48];
        sum_a += (v.x + v.y) + (v.z + v.w);
        float4 u = pA[196 + 48];
        sum_b += (u.x + u.y) + (u.z + u.w);
    }
    // reduce within each 8-lane group
#pragma unroll
    for (int m = 4; m >= 1; m >>= 1) {
        sum_a += __shfl_xor_sync(0xffffffffu, sum_a, m);
        sum_b += __shfl_xor_sync(0xffffffffu, sum_b, m);
    }

    int k = lane & 15;                 // amplitude index owned by this lane
    // per-lane half-angle trig for all 4 wires; fold the row-sign into ss[w]:
    //   ua = ma*c + mp*ss,  up = mp*c - ma*ss
    float cs[4], ss[4];
#pragma unroll
    for (int w = 0; w < 4; w++) {
        float ta = __shfl_sync(0xffffffffu, sum_a, w * 8);
        float tb = __shfl_sync(0xffffffffu, sum_b, w * 8);
        float ang = ((lane < 16) ? ta : tb) * (0.5f / 196.0f);
        float c, s;
        __sincosf(ang, &s, &c);
        if ((k >> (3 - w)) & 1) s = -s;
        cs[w] = c; ss[w] = s;
    }

    // ---- statevector sim: amp(k) per lane ----
    float ar = (k == 0) ? 1.0f : 0.0f;
    float ai = 0.0f;
    const float2* M2 = (const float2*)sM;
#pragma unroll
    for (int l = 0; l < N_LAYERS; l++) {
#pragma unroll
        for (int w = 0; w < 4; w++) {
            int b = (k >> (3 - w)) & 1;
            float2 ma = M2[(l * 4 + w) * 4 + b * 3];      // M[b][b]
            float2 mp = M2[(l * 4 + w) * 4 + b + 1];      // M[b][1-b]
            float c = cs[w], s = ss[w];
            float uar = ma.x * c + mp.x * s;
            float uai = ma.y * c + mp.y * s;
            float upr = mp.x * c - ma.x * s;
            float upi = mp.y * c - ma.y * s;
            float pr = __shfl_xor_sync(0xffffffffu, ar, 8 >> w);
            float pi = __shfl_xor_sync(0xffffffffu, ai, 8 >> w);
            float nr = uar * ar - uai * ai + upr * pr - upi * pi;
            float ni = uar * ai + uai * ar + upr * pi + upi * pr;
            ar = nr; ai = ni;
            if (w < 3) {   // CNOT(w, w+1): permute amps where control bit = 1
                int cm = 8 >> w, tm = 4 >> w;
                int src = (k & cm) ? (lane ^ tm) : lane;
                ar = __shfl_sync(0xffffffffu, ar, src);
                ai = __shfl_sync(0xffffffffu, ai, src);
            }
        }
    }

    // ---- PauliZ expvals ----
    float p = ar * ar + ai * ai;
    float z[4];
#pragma unroll
    for (int w = 0; w < 4; w++) {
        float v = ((k >> (3 - w)) & 1) ? -p : p;
        v += __shfl_xor_sync(0xffffffffu, v, 1);
        v += __shfl_xor_sync(0xffffffffu, v, 2);
        v += __shfl_xor_sync(0xffffffffu, v, 4);
        v += __shfl_xor_sync(0xffffffffu, v, 8);
        z[w] = v;
    }

    // ---- Linear(4,4): lane j (j = k < 4) computes output j of its sample ----
    float o = 0.0f, q = 0.0f;
    if (k < 4) {
        float4 Wr = ((const float4*)Wg)[k];
        o = bg[k] + Wr.x * z[0] + Wr.y * z[1] + Wr.z * z[2] + Wr.w * z[3];
        int s = (lane < 16) ? sA : (sA + 1);
        g_pre[s * 4 + k] = o;
        q = o * o;
    }
    // combine the two samples of this warp, then block-reduce for BN stats
    float o2 = __shfl_xor_sync(0xffffffffu, o, 16);
    float q2 = __shfl_xor_sync(0xffffffffu, q, 16);
    if (lane < 4) {
        atomicAdd(&sAcc[lane],     o + o2);
        atomicAdd(&sAcc[lane + 4], q + q2);
    }
    __syncthreads();
    if (tid < 8) atomicAdd(&g_acc[tid], sAcc[tid]);
}

// ---------------------------------------------------------------------------
// Kernel 2: BatchNorm (training mode, biased variance) over the batch.
// ---------------------------------------------------------------------------
__global__ void bn_kernel(const float* __restrict__ bnw,
                          const float* __restrict__ bnb,
                          float* __restrict__ out) {
    int i = blockIdx.x * blockDim.x + threadIdx.x;   // one sample (float4) each
    float4 pre = ((const float4*)g_pre)[i];
    float po[4] = {pre.x, pre.y, pre.z, pre.w};
    float4 r;
    float* ro = (float*)&r;
    const float inv = 1.0f / (float)BATCH;
#pragma unroll
    for (int j = 0; j < 4; j++) {
        float mu  = g_acc[j] * inv;
        float var = g_acc[4 + j] * inv - mu * mu;
        ro[j] = (po[j] - mu) * rsqrtf(var + BN_EPS) * bnw[j] + bnb[j];
    }
    ((float4*)out)[i] = r;
}

// ---------------------------------------------------------------------------
extern "C" void kernel_launch(void* const* d_in, const int* in_sizes, int n_in,
                              void* d_out, int out_size) {
    const float* x      = (const float*)d_in[0];
    const float* params = (const float*)d_in[1];
    const float* W      = (const float*)d_in[2];
    const float* b      = (const float*)d_in[3];
    const float* bnw    = (const float*)d_in[4];
    const float* bnb    = (const float*)d_in[5];
    float* out = (float*)d_out;

    prep_kernel<<<1, 128>>>(params);
    sim_kernel<<<BATCH / 16, 256>>>(x, W, b);     // 16 samples per 256-thread block
    bn_kernel<<<BATCH / 256, 256>>>(bnw, bnb, out);
}